// round 11
// baseline (speedup 1.0000x reference)
#include <cuda_runtime.h>

#define G_   1024
#define N_   65536
#define D_   128
#define E_   400000

// Scratch (device globals — no allocations allowed)
__device__ __align__(16) float g_A[G_ * 128];      // graph_and_focus @ W1[0:384] + b1 (64 scorer | 64 type cols)
__device__ __align__(16) float g_C[N_ * 128];      // node @ W1[384:512] + A[n2g[node]] (fused per-node table)
__device__ float g_cstop[64];                      // no_more_edges_rep @ scorer_W1[384:516]

// packed f32x2 helpers (full-rate FMA pipe; scalar 3-reg FFMA is half-rate)
__device__ __forceinline__ unsigned long long fma2(unsigned long long a, unsigned long long b,
                                                   unsigned long long c) {
    unsigned long long d;
    asm("fma.rn.f32x2 %0, %1, %2, %3;" : "=l"(d) : "l"(a), "l"(b), "l"(c));
    return d;
}
__device__ __forceinline__ unsigned long long pack2(float lo, float hi) {
    unsigned long long d;
    asm("mov.b64 %0, {%1, %2};" : "=l"(d) : "f"(lo), "f"(hi));
    return d;
}
__device__ __forceinline__ void unpack2(unsigned long long v, float& lo, float& hi) {
    asm("mov.b64 {%0, %1}, %2;" : "=f"(lo), "=f"(hi) : "l"(v));
}

// ---------------------------------------------------------------------------
// kP: cstop (K-split 4 ways). 1 block x 256 threads.
// ---------------------------------------------------------------------------
__global__ void kP(const float* __restrict__ no_more, const float* __restrict__ sW1) {
    __shared__ float part[4][64];
    int tid = threadIdx.x;
    int j = tid & 63, s = tid >> 6;
    float sum = 0.f;
#pragma unroll 3
    for (int k = s * 33; k < s * 33 + 33; k++)
        sum += no_more[k] * sW1[(384 + k) * 64 + j];
    part[s][j] = sum;
    __syncthreads();
    if (tid < 64)
        g_cstop[tid] = part[0][tid] + part[1][tid] + part[2][tid] + part[3][tid];
}

// ---------------------------------------------------------------------------
// kA: per-graph A[g][j] = [imr|pgr|focus] @ W1[0:384] + b1 ; stop logits inline.
// ---------------------------------------------------------------------------
__global__ void kA(const float* __restrict__ imr, const float* __restrict__ pgr,
                   const float* __restrict__ nodes, const int* __restrict__ focus,
                   const float* __restrict__ sW1, const float* __restrict__ sb1,
                   const float* __restrict__ tW1, const float* __restrict__ tb1,
                   const float* __restrict__ sW2, const float* __restrict__ sb2,
                   float* __restrict__ out) {
    __shared__ float xs[8][384];
    __shared__ float sred[8][2];
    int j = threadIdx.x;
    int g0 = blockIdx.x * 8;
#pragma unroll
    for (int r = 0; r < 8; r++) {
        int g = g0 + r;
        xs[r][j]       = imr[g * 128 + j];
        xs[r][128 + j] = pgr[g * 128 + j];
        xs[r][256 + j] = nodes[(size_t)focus[g] * 128 + j];
    }
    __syncthreads();
    bool isS = (j < 64);
    float bias = isS ? sb1[j] : tb1[j - 64];
    const float* W = isS ? (sW1 + j) : (tW1 + (j - 64));
    float acc[8];
#pragma unroll
    for (int r = 0; r < 8; r++) acc[r] = bias;
#pragma unroll 4
    for (int k = 0; k < 384; k++) {
        float w = W[k * 64];
#pragma unroll
        for (int r = 0; r < 8; r++) acc[r] = fmaf(xs[r][k], w, acc[r]);
    }
#pragma unroll
    for (int r = 0; r < 8; r++) g_A[(size_t)(g0 + r) * 128 + j] = acc[r];

    float ws2 = isS ? sW2[j] : 0.f;
    float cst = isS ? g_cstop[j] : 0.f;
#pragma unroll
    for (int r = 0; r < 8; r++) {
        float pv = isS ? fmaxf(acc[r] + cst, 0.f) * ws2 : 0.f;
#pragma unroll
        for (int o = 16; o >= 1; o >>= 1) pv += __shfl_xor_sync(0xffffffffu, pv, o);
        if ((j & 31) == 0 && isS) sred[r][j >> 5] = pv;
    }
    __syncthreads();
    if (j < 8) out[E_ + g0 + j] = sred[j][0] + sred[j][1] + sb2[0];
}

// ---------------------------------------------------------------------------
// kB v3: double-buffered k-chunks in dynamic smem.
//     512 blocks x 512 threads, tile 128x128, thread tile 8 rows x 4 cols,
//     row-pair f32x2 accumulators. Stage chunk c+1 while computing chunk c.
// ---------------------------------------------------------------------------
#define KB_XS (32 * 132)
#define KB_SW (32 * 128)
#define KB_BUF (KB_XS + KB_SW)
#define KB_DYN_BYTES (2 * KB_BUF * 4)

__device__ __forceinline__ void kb_stage(float* __restrict__ xs, float* __restrict__ sw,
                                         const float* __restrict__ nodes_base,
                                         const float* __restrict__ sW1,
                                         const float* __restrict__ tW1,
                                         int kc, int tid) {
    // W chunk [32k x 128j]
    for (int i = tid; i < 32 * 128; i += 512) {
        int k = i >> 7, j = i & 127;
        sw[k * 128 + j] = (j < 64) ? sW1[(384 + kc + k) * 64 + j]
                                   : tW1[(384 + kc + k) * 64 + (j - 64)];
    }
    // x chunk transposed [32k x 128r]
    for (int f = tid; f < 1024; f += 512) {
        int r = f >> 3, kq = (f & 7) << 2;
        float4 v = *(const float4*)(nodes_base + (size_t)r * 128 + kc + kq);
        xs[(kq + 0) * 132 + r] = v.x;
        xs[(kq + 1) * 132 + r] = v.y;
        xs[(kq + 2) * 132 + r] = v.z;
        xs[(kq + 3) * 132 + r] = v.w;
    }
}

__global__ __launch_bounds__(512, 2) void kB(const float* __restrict__ nodes,
                                             const float* __restrict__ sW1,
                                             const float* __restrict__ tW1,
                                             const int* __restrict__ n2g) {
    extern __shared__ float dyn[];
    int tid = threadIdx.x;
    int tx = tid & 31, ty = tid >> 5;
    int c0 = tx * 4, r0 = ty * 8;
    int row0 = blockIdx.x * 128;
    const float* nbase = nodes + (size_t)row0 * 128;

    unsigned long long acc[4][4];   // [row-pair][col]
#pragma unroll
    for (int i = 0; i < 4; i++)
#pragma unroll
        for (int j = 0; j < 4; j++) acc[i][j] = 0ull;

    kb_stage(dyn, dyn + KB_XS, nbase, sW1, tW1, 0, tid);
    __syncthreads();

    for (int c = 0; c < 4; c++) {
        int cur = c & 1, nxt = cur ^ 1;
        if (c < 3)
            kb_stage(dyn + nxt * KB_BUF, dyn + nxt * KB_BUF + KB_XS,
                     nbase, sW1, tW1, (c + 1) * 32, tid);
        const float* xs = dyn + cur * KB_BUF;
        const float* sw = xs + KB_XS;
#pragma unroll 8
        for (int k = 0; k < 32; k++) {
            const unsigned long long* xp = (const unsigned long long*)(xs + k * 132 + r0);
            unsigned long long x0 = xp[0], x1 = xp[1], x2 = xp[2], x3 = xp[3];
            float4 w = *(const float4*)(sw + k * 128 + c0);
            unsigned long long w0 = pack2(w.x, w.x), w1 = pack2(w.y, w.y);
            unsigned long long w2 = pack2(w.z, w.z), w3 = pack2(w.w, w.w);
            acc[0][0] = fma2(x0, w0, acc[0][0]); acc[0][1] = fma2(x0, w1, acc[0][1]);
            acc[0][2] = fma2(x0, w2, acc[0][2]); acc[0][3] = fma2(x0, w3, acc[0][3]);
            acc[1][0] = fma2(x1, w0, acc[1][0]); acc[1][1] = fma2(x1, w1, acc[1][1]);
            acc[1][2] = fma2(x1, w2, acc[1][2]); acc[1][3] = fma2(x1, w3, acc[1][3]);
            acc[2][0] = fma2(x2, w0, acc[2][0]); acc[2][1] = fma2(x2, w1, acc[2][1]);
            acc[2][2] = fma2(x2, w2, acc[2][2]); acc[2][3] = fma2(x2, w3, acc[2][3]);
            acc[3][0] = fma2(x3, w0, acc[3][0]); acc[3][1] = fma2(x3, w1, acc[3][1]);
            acc[3][2] = fma2(x3, w2, acc[3][2]); acc[3][3] = fma2(x3, w3, acc[3][3]);
        }
        __syncthreads();   // publishes next buffer; protects cur buffer for reuse at c+2
    }
    // epilogue: unpack, add A[n2g[row]] (n2g sorted -> near-sequential), store
#pragma unroll
    for (int i = 0; i < 4; i++) {
        float lo[4], hi[4];
#pragma unroll
        for (int j = 0; j < 4; j++) unpack2(acc[i][j], lo[j], hi[j]);
        int rowA = row0 + r0 + 2 * i;
        int gA = n2g[rowA], gB = n2g[rowA + 1];
        float4 a0 = *(const float4*)(g_A + (size_t)gA * 128 + c0);
        float4 b0 = *(const float4*)(g_A + (size_t)gB * 128 + c0);
        *(float4*)(g_C + (size_t)rowA * 128 + c0) =
            make_float4(lo[0] + a0.x, lo[1] + a0.y, lo[2] + a0.z, lo[3] + a0.w);
        *(float4*)(g_C + (size_t)(rowA + 1) * 128 + c0) =
            make_float4(hi[0] + b0.x, hi[1] + b0.y, hi[2] + b0.z, hi[3] + b0.w);
    }
}

// ---------------------------------------------------------------------------
// kE: 1 edge per warp, lane owns 4 combined cols (lanes 0-15 scorer, 16-31
//     type). Scalar dist fma vs w512 regs; 1-deep prefetch of targets->C chain.
//     (measured 74.0us; unchanged)
// ---------------------------------------------------------------------------
__global__ __launch_bounds__(256) void kE(const int* __restrict__ targets,
                   const float4* __restrict__ feats4,
                   const float* __restrict__ sW1, const float* __restrict__ tW1,
                   const float* __restrict__ sW2, const float* __restrict__ sb2,
                   const float* __restrict__ tW2, const float* __restrict__ tb2,
                   const float* __restrict__ dist_table,
                   float* __restrict__ out) {
    __shared__ float sdt[10];
    if (threadIdx.x < 10) sdt[threadIdx.x] = dist_table[threadIdx.x];
    __syncthreads();

    int lane = threadIdx.x & 31;
    bool isS = (lane < 16);
    int cbase = (lane & 15) * 4;
    const float* W1 = isS ? sW1 : tW1;
    float4 w512 = *(const float4*)(W1 + 512 * 64 + cbase);
    float4 w513 = *(const float4*)(W1 + 513 * 64 + cbase);
    float4 w514 = *(const float4*)(W1 + 514 * 64 + cbase);
    float4 w515 = *(const float4*)(W1 + 515 * 64 + cbase);
    float4 u0, u1, u2;
    if (isS) {
        u0 = *(const float4*)(sW2 + cbase);
        u1 = make_float4(0.f, 0.f, 0.f, 0.f);
        u2 = u1;
    } else {
        u0.x = tW2[(cbase + 0) * 3]; u0.y = tW2[(cbase + 1) * 3];
        u0.z = tW2[(cbase + 2) * 3]; u0.w = tW2[(cbase + 3) * 3];
        u1.x = tW2[(cbase + 0) * 3 + 1]; u1.y = tW2[(cbase + 1) * 3 + 1];
        u1.z = tW2[(cbase + 2) * 3 + 1]; u1.w = tW2[(cbase + 3) * 3 + 1];
        u2.x = tW2[(cbase + 0) * 3 + 2]; u2.y = tW2[(cbase + 1) * 3 + 2];
        u2.z = tW2[(cbase + 2) * 3 + 2]; u2.w = tW2[(cbase + 3) * 3 + 2];
    }
    float sb2v = sb2[0];
    float tb0 = tb2[0], tb1v = tb2[1], tb2v = tb2[2];
    const float4* C4 = (const float4*)g_C;
    float* outT = out + (E_ + G_);

    int gw = (blockIdx.x * blockDim.x + threadIdx.x) >> 5;
    int nw = (gridDim.x * blockDim.x) >> 5;

    int e = gw;
    float4 f, c;
    if (e < E_) {
        int t = targets[e];
        f = feats4[e];
        c = C4[(size_t)t * 32 + lane];
    }
    while (e < E_) {
        int e2 = e + nw;
        float4 f2, c2;
        if (e2 < E_) {
            int t2 = targets[e2];
            f2 = feats4[e2];
            c2 = C4[(size_t)t2 * 32 + lane];
        }
        float dv = sdt[(int)fminf(f.x, 9.0f)];
        float hx = fmaxf(fmaf(dv, w512.x, fmaf(f.y, w513.x, fmaf(f.z, w514.x, fmaf(f.w, w515.x, c.x)))), 0.f);
        float hy = fmaxf(fmaf(dv, w512.y, fmaf(f.y, w513.y, fmaf(f.z, w514.y, fmaf(f.w, w515.y, c.y)))), 0.f);
        float hz = fmaxf(fmaf(dv, w512.z, fmaf(f.y, w513.z, fmaf(f.z, w514.z, fmaf(f.w, w515.z, c.z)))), 0.f);
        float hw = fmaxf(fmaf(dv, w512.w, fmaf(f.y, w513.w, fmaf(f.z, w514.w, fmaf(f.w, w515.w, c.w)))), 0.f);
        float v0 = fmaf(hx, u0.x, fmaf(hy, u0.y, fmaf(hz, u0.z, hw * u0.w)));
        float v1 = fmaf(hx, u1.x, fmaf(hy, u1.y, fmaf(hz, u1.z, hw * u1.w)));
        float v2 = fmaf(hx, u2.x, fmaf(hy, u2.y, fmaf(hz, u2.z, hw * u2.w)));
        float p = isS ? v0 : v1;
        float q = __shfl_xor_sync(0xffffffffu, v0, 16);
        q = isS ? q : v2;
#pragma unroll
        for (int o = 1; o <= 8; o <<= 1) {
            p += __shfl_xor_sync(0xffffffffu, p, o);
            q += __shfl_xor_sync(0xffffffffu, q, o);
        }
        if (lane == 0) {
            out[e] = p + sb2v;          // scorer logit
            outT[3 * e] = q + tb0;      // type logit 0
        }
        if (lane == 16) {
            outT[3 * e + 1] = p + tb1v; // type logit 1
            outT[3 * e + 2] = q + tb2v; // type logit 2
        }
        e = e2; f = f2; c = c2;
    }
}

// ---------------------------------------------------------------------------
extern "C" void kernel_launch(void* const* d_in, const int* in_sizes, int n_in,
                              void* d_out, int out_size) {
    const float* imr     = (const float*)d_in[0];
    const float* pgr     = (const float*)d_in[1];
    const float* nodes   = (const float*)d_in[2];
    const int*   focus   = (const int*)d_in[3];
    const int*   n2g     = (const int*)d_in[4];
    const int*   targets = (const int*)d_in[5];
    const float* feats   = (const float*)d_in[6];
    int p = 7;
    if (p < n_in && in_sizes[p] == 1) p++;  // skip num_graphs_in_batch scalar if present
    const float* dist_table = (const float*)d_in[p++];  // [10]
    const float* no_more    = (const float*)d_in[p++];  // [132]
    const float* sW1 = (const float*)d_in[p++];         // [516,64]
    const float* sb1 = (const float*)d_in[p++];         // [64]
    const float* sW2 = (const float*)d_in[p++];         // [64]
    const float* sb2 = (const float*)d_in[p++];         // [1]
    const float* tW1 = (const float*)d_in[p++];         // [516,64]
    const float* tb1 = (const float*)d_in[p++];         // [64]
    const float* tW2 = (const float*)d_in[p++];         // [64,3]
    const float* tb2 = (const float*)d_in[p++];         // [3]
    float* out = (float*)d_out;

    cudaFuncSetAttribute(kB, cudaFuncAttributeMaxDynamicSharedMemorySize, KB_DYN_BYTES);

    kP<<<1, 256>>>(no_more, sW1);
    kA<<<G_ / 8, 128>>>(imr, pgr, nodes, focus, sW1, sb1, tW1, tb1, sW2, sb2, out);
    kB<<<N_ / 128, 512, KB_DYN_BYTES>>>(nodes, sW1, tW1, n2g);
    kE<<<1184, 256>>>(targets, (const float4*)feats, sW1, tW1, sW2, sb2, tW2, tb2,
                      dist_table, out);
}